// round 3
// baseline (speedup 1.0000x reference)
#include <cuda_runtime.h>
#include <cstddef>

#define NN 100000
#define NE 3200000
#define FIN 512
#define HID 64
#define NC  64
#define KHOPS 20

// ---------------- scratch (device globals; no allocation allowed) ------------
__device__ float g_h[(size_t)NN * HID];      // MLP hidden
__device__ float g_xA[(size_t)NN * NC];      // ping
__device__ float g_xB[(size_t)NN * NC];      // pong
__device__ int   g_counts[NN];
__device__ int   g_rowptr[NN + 1];
__device__ int   g_widx[NN];
__device__ int2  g_edges[NE];                // (sender, weight-bits) sorted by receiver

// ---------------- CSR build --------------------------------------------------
__global__ void k_zero_counts() {
    int i = blockIdx.x * blockDim.x + threadIdx.x;
    if (i < NN) g_counts[i] = 0;
}

__global__ void k_hist(const int* __restrict__ rcv) {
    int e = blockIdx.x * blockDim.x + threadIdx.x;
    if (e < NE) atomicAdd(&g_counts[rcv[e]], 1);
}

__global__ void k_scan() {
    __shared__ int sm[1024];
    const int t = threadIdx.x;
    const int CH = (NN + 1023) / 1024;             // 98
    int beg = t * CH;
    int end = beg + CH; if (end > NN) end = NN;
    if (beg > NN) beg = NN;
    int s = 0;
    for (int i = beg; i < end; ++i) s += g_counts[i];
    sm[t] = s;
    __syncthreads();
    for (int d = 1; d < 1024; d <<= 1) {
        int add = (t >= d) ? sm[t - d] : 0;
        __syncthreads();
        sm[t] += add;
        __syncthreads();
    }
    int off = (t == 0) ? 0 : sm[t - 1];
    for (int i = beg; i < end; ++i) {
        g_rowptr[i] = off;
        g_widx[i]   = off;
        off += g_counts[i];
    }
    if (t == 1023) g_rowptr[NN] = sm[1023];
}

__global__ void k_scatter(const int* __restrict__ snd, const int* __restrict__ rcv,
                          const float* __restrict__ w) {
    int e = blockIdx.x * blockDim.x + threadIdx.x;
    if (e >= NE) return;
    int r = rcv[e];
    int pos = atomicAdd(&g_widx[r], 1);
    g_edges[pos] = make_int2(snd[e], __float_as_int(w[e]));
}

// ---------------- tiled fp32 GEMM: C[M,64] = act(A[M,K]@B[K,64] + bias) ------
template <int K, bool RELU>
__global__ __launch_bounds__(256) void k_gemm(const float* __restrict__ A,
                                              const float* __restrict__ B,
                                              const float* __restrict__ bias,
                                              float* __restrict__ C, int M) {
    constexpr int BM = 128, BN = 64, BK = 16;
    __shared__ float As[BK][BM + 4];
    __shared__ float Bs[BK][BN];
    const int tid = threadIdx.x;
    const int block_row = blockIdx.x * BM;
    const int tx = tid & 15;        // 16 col-groups of 4
    const int ty = tid >> 4;        // 16 row-groups of 8
    float acc[8][4];
#pragma unroll
    for (int i = 0; i < 8; ++i)
#pragma unroll
        for (int j = 0; j < 4; ++j) acc[i][j] = 0.f;

    const int ar = tid >> 2;              // 0..63
    const int ac = (tid & 3) << 2;        // 0,4,8,12
    const int br = tid >> 4;              // 0..15
    const int bc = (tid & 15) << 2;       // 0..60

    for (int k0 = 0; k0 < K; k0 += BK) {
#pragma unroll
        for (int i = 0; i < 2; ++i) {
            int row = block_row + ar + i * 64;
            float4 v = make_float4(0.f, 0.f, 0.f, 0.f);
            if (row < M) v = *(const float4*)(A + (size_t)row * K + k0 + ac);
            As[ac + 0][ar + i * 64] = v.x;
            As[ac + 1][ar + i * 64] = v.y;
            As[ac + 2][ar + i * 64] = v.z;
            As[ac + 3][ar + i * 64] = v.w;
        }
        *(float4*)&Bs[br][bc] = *(const float4*)(B + (size_t)(k0 + br) * BN + bc);
        __syncthreads();
#pragma unroll
        for (int kk = 0; kk < BK; ++kk) {
            float4 a0 = *(const float4*)&As[kk][ty * 8 + 0];
            float4 a1 = *(const float4*)&As[kk][ty * 8 + 4];
            float4 b0 = *(const float4*)&Bs[kk][tx * 4];
            float a[8] = {a0.x, a0.y, a0.z, a0.w, a1.x, a1.y, a1.z, a1.w};
            float b[4] = {b0.x, b0.y, b0.z, b0.w};
#pragma unroll
            for (int i = 0; i < 8; ++i)
#pragma unroll
                for (int j = 0; j < 4; ++j) acc[i][j] += a[i] * b[j];
        }
        __syncthreads();
    }
#pragma unroll
    for (int i = 0; i < 8; ++i) {
        int row = block_row + ty * 8 + i;
        if (row < M) {
            float4 v;
            v.x = acc[i][0] + bias[tx * 4 + 0];
            v.y = acc[i][1] + bias[tx * 4 + 1];
            v.z = acc[i][2] + bias[tx * 4 + 2];
            v.w = acc[i][3] + bias[tx * 4 + 3];
            if (RELU) {
                v.x = fmaxf(v.x, 0.f); v.y = fmaxf(v.y, 0.f);
                v.z = fmaxf(v.z, 0.f); v.w = fmaxf(v.w, 0.f);
            }
            *(float4*)(C + (size_t)row * BN + tx * 4) = v;
        }
    }
}

// ---------------- gating init: out = sigmoid(x·Wg+bg) * x  (hop 0) -----------
__global__ __launch_bounds__(256) void k_gate_init(const float* __restrict__ Wg,
                                                   const float* __restrict__ bg,
                                                   float* __restrict__ out) {
    int gw = (blockIdx.x * blockDim.x + threadIdx.x) >> 5;
    int lane = threadIdx.x & 31;
    if (gw >= NN) return;
    const float2* x2 = (const float2*)g_xA;
    float2 v = x2[(size_t)gw * 32 + lane];
    float part = v.x * Wg[2 * lane] + v.y * Wg[2 * lane + 1];
#pragma unroll
    for (int o = 16; o; o >>= 1) part += __shfl_xor_sync(0xffffffffu, part, o);
    float gsc = 1.f / (1.f + __expf(-(part + bg[0])));
    float2 o2 = make_float2(gsc * v.x, gsc * v.y);
    ((float2*)out)[(size_t)gw * 32 + lane] = o2;
}

// ---------------- SpMM (gather CSR) + fused gated accumulation ---------------
__global__ __launch_bounds__(256) void k_spmm_gate(int ab,
                                                   const float* __restrict__ Wg,
                                                   const float* __restrict__ bg,
                                                   float* __restrict__ out) {
    int gw = (blockIdx.x * blockDim.x + threadIdx.x) >> 5;  // node (warp per node)
    int lane = threadIdx.x & 31;
    if (gw >= NN) return;
    const float2* __restrict__ x2 = ab ? (const float2*)g_xB : (const float2*)g_xA;
    float2* __restrict__ y2       = ab ? (float2*)g_xA       : (float2*)g_xB;

    int beg = g_rowptr[gw];
    int end = g_rowptr[gw + 1];
    float2 acc = make_float2(0.f, 0.f);

    int e = beg;
    for (; e + 4 <= end; e += 4) {
        int2 e0 = g_edges[e + 0];
        int2 e1 = g_edges[e + 1];
        int2 e2 = g_edges[e + 2];
        int2 e3 = g_edges[e + 3];
        float2 v0 = x2[(size_t)e0.x * 32 + lane];
        float2 v1 = x2[(size_t)e1.x * 32 + lane];
        float2 v2 = x2[(size_t)e2.x * 32 + lane];
        float2 v3 = x2[(size_t)e3.x * 32 + lane];
        float w0 = __int_as_float(e0.y), w1 = __int_as_float(e1.y);
        float w2 = __int_as_float(e2.y), w3 = __int_as_float(e3.y);
        acc.x += w0 * v0.x; acc.y += w0 * v0.y;
        acc.x += w1 * v1.x; acc.y += w1 * v1.y;
        acc.x += w2 * v2.x; acc.y += w2 * v2.y;
        acc.x += w3 * v3.x; acc.y += w3 * v3.y;
    }
    for (; e < end; ++e) {
        int2 ep = g_edges[e];
        float w = __int_as_float(ep.y);
        float2 v = x2[(size_t)ep.x * 32 + lane];
        acc.x += w * v.x; acc.y += w * v.y;
    }

    y2[(size_t)gw * 32 + lane] = acc;

    // fused gated-sum accumulation
    float part = acc.x * Wg[2 * lane] + acc.y * Wg[2 * lane + 1];
#pragma unroll
    for (int o = 16; o; o >>= 1) part += __shfl_xor_sync(0xffffffffu, part, o);
    float gsc = 1.f / (1.f + __expf(-(part + bg[0])));
    float2* o2 = (float2*)out;
    float2 cur = o2[(size_t)gw * 32 + lane];
    cur.x += gsc * acc.x;
    cur.y += gsc * acc.y;
    o2[(size_t)gw * 32 + lane] = cur;
}

// ---------------- launch -----------------------------------------------------
extern "C" void kernel_launch(void* const* d_in, const int* in_sizes, int n_in,
                              void* d_out, int out_size) {
    const float* X   = (const float*)d_in[0];
    const float* ew  = (const float*)d_in[1];
    const float* W1  = (const float*)d_in[2];
    const float* b1  = (const float*)d_in[3];
    const float* W2  = (const float*)d_in[4];
    const float* b2  = (const float*)d_in[5];
    const float* Wg  = (const float*)d_in[6];
    const float* bg  = (const float*)d_in[7];
    const int*   snd = (const int*)d_in[8];
    const int*   rcv = (const int*)d_in[9];
    float* out = (float*)d_out;

    void* p;
    cudaGetSymbolAddress(&p, g_h);  float* hptr = (float*)p;
    cudaGetSymbolAddress(&p, g_xA); float* xA   = (float*)p;

    // CSR build (once per launch; deterministic up to fp-irrelevant intra-row order)
    k_zero_counts<<<(NN + 255) / 256, 256>>>();
    k_hist<<<(NE + 255) / 256, 256>>>(rcv);
    k_scan<<<1, 1024>>>();
    k_scatter<<<(NE + 255) / 256, 256>>>(snd, rcv, ew);

    // MLP: h = relu(X@W1+b1); logits = h@W2+b2 -> g_xA
    dim3 gg((NN + 127) / 128);
    k_gemm<FIN, true ><<<gg, 256>>>(X,    W1, b1, hptr, NN);
    k_gemm<HID, false><<<gg, 256>>>(hptr, W2, b2, xA,   NN);

    // hop 0 gating
    const int SPB = (NN + 7) / 8;   // 8 warps/block
    k_gate_init<<<SPB, 256>>>(Wg, bg, out);

    // 20 propagations, ping-pong, gating fused
    for (int k = 0; k < KHOPS; ++k)
        k_spmm_gate<<<SPB, 256>>>(k & 1, Wg, bg, out);
}